// round 3
// baseline (speedup 1.0000x reference)
#include <cuda_runtime.h>
#include <cstdint>

#define B_   128
#define T_   512
#define E_   512
#define H_   1024
#define G3H_ 3072
#define NROW 65536   // B*T

#define NCTA 128     // CTAs in persistent recurrence
#define COLS 8       // h-columns per CTA
#define WROW 24      // 3 gates * COLS weight rows per CTA
#define WPAD 1028    // W smem row stride (words) -> conflict-free B reads
#define ASTRIDE 20   // h-tile smem row stride (words)
#define ASTAGE (128*ASTRIDE)
#define REC_SMEM ((WROW*WPAD + 3*ASTAGE) * 4)

// ---------------- device scratch ----------------
__device__ float g_x0 [(size_t)NROW * E_];
__device__ float g_y0 [(size_t)NROW * H_];
__device__ float g_gx0[(size_t)NROW * G3H_];
__device__ float g_gx1[(size_t)NROW * G3H_];
__device__ float g_wih0[G3H_ * E_];
__device__ float g_wih1[G3H_ * H_];
__device__ float g_h0[2][B_ * H_];
__device__ float g_h1[2][B_ * H_];
__device__ unsigned g_bar0;
__device__ unsigned g_bar1;

// ---------------- helpers ----------------
__device__ __forceinline__ float tf32r(float x) {
    uint32_t u;
    asm("cvt.rna.tf32.f32 %0, %1;" : "=r"(u) : "f"(x));
    return __uint_as_float(u);
}
__device__ __forceinline__ void cp16(void* s, const void* g) {
    uint32_t sa = (uint32_t)__cvta_generic_to_shared(s);
    asm volatile("cp.async.cg.shared.global [%0], [%1], 16;" :: "r"(sa), "l"(g));
}
__device__ __forceinline__ void cpcommit() { asm volatile("cp.async.commit_group;"); }
__device__ __forceinline__ void cpwait1()  { asm volatile("cp.async.wait_group 1;"); }
__device__ __forceinline__ void cpwait0()  { asm volatile("cp.async.wait_group 0;"); }

__device__ __forceinline__ void mma8(float c[4], const uint32_t a[4], const uint32_t b[2]) {
    asm volatile(
        "mma.sync.aligned.m16n8k8.row.col.f32.tf32.tf32.f32 "
        "{%0,%1,%2,%3}, {%4,%5,%6,%7}, {%8,%9}, {%0,%1,%2,%3};"
        : "+f"(c[0]), "+f"(c[1]), "+f"(c[2]), "+f"(c[3])
        : "r"(a[0]), "r"(a[1]), "r"(a[2]), "r"(a[3]), "r"(b[0]), "r"(b[1]));
}

__device__ __forceinline__ void grid_sync(unsigned* bar, unsigned target) {
    __syncthreads();
    if (threadIdx.x == 0) {
        __threadfence();
        atomicAdd(bar, 1u);
        while (*((volatile unsigned*)bar) < target) { __nanosleep(32); }
        __threadfence();
    }
    __syncthreads();
}

// ---------------- setup kernels ----------------
__global__ void k_init() {
    size_t i = (size_t)blockIdx.x * blockDim.x + threadIdx.x;
    if (i == 0) { g_bar0 = 0; g_bar1 = 0; }
    if (i < (size_t)2 * B_ * H_) { (&g_h0[0][0])[i] = 0.f; (&g_h1[0][0])[i] = 0.f; }
}

__global__ void k_round(const float* __restrict__ in, float* __restrict__ out, int n) {
    for (int i = blockIdx.x * blockDim.x + threadIdx.x; i < n; i += gridDim.x * blockDim.x)
        out[i] = tf32r(in[i]);
}

__global__ void k_gather(const int* __restrict__ src, const float* __restrict__ emb,
                         float* __restrict__ x0) {
    int row = blockIdx.x;
    int v = src[row];
    const float* e = emb + (size_t)v * E_;
    float* o = x0 + (size_t)row * E_;
    for (int j = threadIdx.x; j < E_; j += blockDim.x) o[j] = tf32r(e[j]);
}

// ---------------- big input-projection GEMM: C[M,3072] = A[M,K]*W[3072,K]^T + bias ----------------
__device__ __forceinline__ void gemm_load(float (*As)[20], float (*Ws)[20],
                                          const float* Ab, const float* Wb,
                                          int K, int kt, int tid) {
    #pragma unroll
    for (int i = 0; i < 2; i++) {
        int id = tid + 256 * i;
        int r = id >> 2, s = id & 3;
        cp16(&As[r][s * 4], Ab + (size_t)r * K + kt * 16 + s * 4);
        cp16(&Ws[r][s * 4], Wb + (size_t)r * K + kt * 16 + s * 4);
    }
    cpcommit();
}

__global__ __launch_bounds__(256) void k_gemm(const float* __restrict__ A,
                                              const float* __restrict__ W,
                                              const float* __restrict__ bias,
                                              float* __restrict__ C, int K) {
    __shared__ float As[2][128][20];
    __shared__ float Ws[2][128][20];
    int tid = threadIdx.x;
    int lane = tid & 31, wid = tid >> 5;
    int g = lane >> 2, tg = lane & 3;
    int wM = wid & 1, wN = wid >> 1;
    const float* Ab = A + (size_t)blockIdx.y * 128 * K;
    const float* Wb = W + (size_t)blockIdx.x * 128 * K;

    float c[4][4][4];
    #pragma unroll
    for (int i = 0; i < 4; i++)
        #pragma unroll
        for (int j = 0; j < 4; j++)
            #pragma unroll
            for (int e = 0; e < 4; e++) c[i][j][e] = 0.f;

    int KIT = K >> 4;
    gemm_load(As[0], Ws[0], Ab, Wb, K, 0, tid);

    for (int kt = 0; kt < KIT; kt++) {
        int cur = kt & 1;
        if (kt + 1 < KIT) { gemm_load(As[cur ^ 1], Ws[cur ^ 1], Ab, Wb, K, kt + 1, tid); cpwait1(); }
        else cpwait0();
        __syncthreads();
        #pragma unroll
        for (int ks = 0; ks < 2; ks++) {
            uint32_t a[4][4], b[4][2];
            #pragma unroll
            for (int mt = 0; mt < 4; mt++) {
                int r0 = wM * 64 + mt * 16 + g;
                a[mt][0] = __float_as_uint(As[cur][r0    ][ks * 8 + tg]);
                a[mt][1] = __float_as_uint(As[cur][r0 + 8][ks * 8 + tg]);
                a[mt][2] = __float_as_uint(As[cur][r0    ][ks * 8 + tg + 4]);
                a[mt][3] = __float_as_uint(As[cur][r0 + 8][ks * 8 + tg + 4]);
            }
            #pragma unroll
            for (int nt = 0; nt < 4; nt++) {
                int n0 = wN * 32 + nt * 8 + g;
                b[nt][0] = __float_as_uint(Ws[cur][n0][ks * 8 + tg]);
                b[nt][1] = __float_as_uint(Ws[cur][n0][ks * 8 + tg + 4]);
            }
            #pragma unroll
            for (int mt = 0; mt < 4; mt++)
                #pragma unroll
                for (int nt = 0; nt < 4; nt++) mma8(c[mt][nt], a[mt], b[nt]);
        }
        __syncthreads();
    }

    size_t row0 = (size_t)blockIdx.y * 128;
    int col0 = blockIdx.x * 128 + wN * 32;
    #pragma unroll
    for (int mt = 0; mt < 4; mt++)
        #pragma unroll
        for (int nt = 0; nt < 4; nt++)
            #pragma unroll
            for (int e = 0; e < 4; e++) {
                size_t row = row0 + wM * 64 + mt * 16 + g + (e >> 1) * 8;
                int col = col0 + nt * 8 + 2 * tg + (e & 1);
                C[row * G3H_ + col] = c[mt][nt][e] + bias[col];
            }
}

// ---------------- persistent recurrence: one layer, 512 steps, weights SMEM-resident ----------------
__global__ __launch_bounds__(256) void k_rec_persist(
    const float* __restrict__ W,     // whh raw fp32 [3072][1024]
    const float* __restrict__ gx,    // [B][T][3H] fp32
    const float* __restrict__ bhh,   // [3H]
    float* __restrict__ hbuf,        // [2][B*H] ping-pong
    float* __restrict__ yout,        // [B][T][H] or nullptr
    float* __restrict__ outf,        // [B][H] final hidden (fp32)
    unsigned* __restrict__ bar) {
    extern __shared__ float smem[];
    float* Ws = smem;                    // [WROW][WPAD]
    float* As = smem + WROW * WPAD;      // 3 stages [128][ASTRIDE]

    int tid = threadIdx.x;
    int lane = tid & 31, wid = tid >> 5;   // wid = wM (0..7), nN = 1
    int g = lane >> 2, tg = lane & 3;
    int nb = blockIdx.x * COLS;

    // load + tf32-round resident weights: smem row j -> global row (j/8)*1024 + nb + (j%8)
    for (int i = tid; i < WROW * 1024; i += 256) {
        int j = i >> 10, k = i & 1023;
        int grow = (j >> 3) * H_ + nb + (j & 7);
        Ws[j * WPAD + k] = tf32r(W[(size_t)grow * H_ + k]);
    }
    __syncthreads();

    for (int t = 0; t < T_; t++) {
        const float* hin = hbuf + (size_t)(t & 1) * (B_ * H_);
        float* hout = hbuf + (size_t)((t + 1) & 1) * (B_ * H_);

        float c[3][4];
        #pragma unroll
        for (int j = 0; j < 3; j++)
            #pragma unroll
            for (int e = 0; e < 4; e++) c[j][e] = 0.f;

        // prefetch stages 0,1
        #pragma unroll
        for (int s = 0; s < 2; s++) {
            float* dst = As + s * ASTAGE;
            #pragma unroll
            for (int i = 0; i < 2; i++) {
                int idx = tid + 256 * i;
                int r = idx >> 2, sc = idx & 3;
                cp16(dst + r * ASTRIDE + sc * 4, hin + (size_t)r * H_ + s * 16 + sc * 4);
            }
            cpcommit();
        }

        for (int kt = 0; kt < 64; kt++) {
            cpwait1();
            __syncthreads();
            // prefetch kt+2 (always commit so group count stays uniform)
            if (kt + 2 < 64) {
                float* dst = As + ((kt + 2) % 3) * ASTAGE;
                #pragma unroll
                for (int i = 0; i < 2; i++) {
                    int idx = tid + 256 * i;
                    int r = idx >> 2, sc = idx & 3;
                    cp16(dst + r * ASTRIDE + sc * 4, hin + (size_t)r * H_ + (kt + 2) * 16 + sc * 4);
                }
            }
            cpcommit();

            const float* A = As + (kt % 3) * ASTAGE;
            #pragma unroll
            for (int ks = 0; ks < 2; ks++) {
                int ko = ks * 8;
                uint32_t a[4];
                int r0 = wid * 16 + g;
                a[0] = __float_as_uint(A[r0 * ASTRIDE + ko + tg]);
                a[1] = __float_as_uint(A[(r0 + 8) * ASTRIDE + ko + tg]);
                a[2] = __float_as_uint(A[r0 * ASTRIDE + ko + tg + 4]);
                a[3] = __float_as_uint(A[(r0 + 8) * ASTRIDE + ko + tg + 4]);
                #pragma unroll
                for (int gt = 0; gt < 3; gt++) {
                    uint32_t b[2];
                    int j = gt * COLS + g;
                    b[0] = __float_as_uint(Ws[j * WPAD + kt * 16 + ko + tg]);
                    b[1] = __float_as_uint(Ws[j * WPAD + kt * 16 + ko + tg + 4]);
                    mma8(c[gt], a, b);
                }
            }
        }

        // epilogue: fused GRU pointwise
        #pragma unroll
        for (int e = 0; e < 4; e++) {
            int row = wid * 16 + g + (e >> 1) * 8;
            int lc = 2 * tg + (e & 1);
            int col = nb + lc;
            const float* gxr = gx + (size_t)row * (T_ * G3H_) + (size_t)t * G3H_;
            float xr = gxr[col], xz = gxr[H_ + col], xn = gxr[2 * H_ + col];
            float hr = c[0][e] + bhh[col];
            float hz = c[1][e] + bhh[H_ + col];
            float hn = c[2][e] + bhh[2 * H_ + col];
            float rr = 1.f / (1.f + expf(-(xr + hr)));
            float zz = 1.f / (1.f + expf(-(xz + hz)));
            float nn = tanhf(xn + rr * hn);
            float hold = hin[(size_t)row * H_ + col];
            float hnew = (1.f - zz) * nn + zz * hold;
            float hq = tf32r(hnew);
            hout[(size_t)row * H_ + col] = hq;
            if (yout) yout[(size_t)row * (T_ * H_) + (size_t)t * H_ + col] = hq;
            if (t == T_ - 1) outf[(size_t)row * H_ + col] = hnew;
        }

        if (t != T_ - 1) grid_sync(bar, (unsigned)(t + 1) * NCTA);
    }
}

// ---------------- launch ----------------
extern "C" void kernel_launch(void* const* d_in, const int* in_sizes, int n_in,
                              void* d_out, int out_size) {
    const int*   src  = (const int*)d_in[0];
    const float* emb  = (const float*)d_in[1];
    const float* wih0 = (const float*)d_in[2];
    const float* whh0 = (const float*)d_in[3];
    const float* bih0 = (const float*)d_in[4];
    const float* bhh0 = (const float*)d_in[5];
    const float* wih1 = (const float*)d_in[6];
    const float* whh1 = (const float*)d_in[7];
    const float* bih1 = (const float*)d_in[8];
    const float* bhh1 = (const float*)d_in[9];
    float* out = (float*)d_out;

    float *x0, *y0, *gx0, *gx1, *pwih0, *pwih1, *h0, *h1;
    unsigned *bar0, *bar1;
    cudaGetSymbolAddress((void**)&x0,    g_x0);
    cudaGetSymbolAddress((void**)&y0,    g_y0);
    cudaGetSymbolAddress((void**)&gx0,   g_gx0);
    cudaGetSymbolAddress((void**)&gx1,   g_gx1);
    cudaGetSymbolAddress((void**)&pwih0, g_wih0);
    cudaGetSymbolAddress((void**)&pwih1, g_wih1);
    cudaGetSymbolAddress((void**)&h0,    g_h0);
    cudaGetSymbolAddress((void**)&h1,    g_h1);
    cudaGetSymbolAddress((void**)&bar0,  g_bar0);
    cudaGetSymbolAddress((void**)&bar1,  g_bar1);

    cudaFuncSetAttribute(k_rec_persist, cudaFuncAttributeMaxDynamicSharedMemorySize, REC_SMEM);

    k_init<<<(2 * B_ * H_ + 255) / 256, 256>>>();
    k_round<<<256, 256>>>(wih0, pwih0, G3H_ * E_);
    k_round<<<256, 256>>>(wih1, pwih1, G3H_ * H_);
    k_gather<<<NROW, 128>>>(src, emb, x0);

    // layer 0 input projection: [65536,512] x [512->3072]
    k_gemm<<<dim3(24, 512), 256>>>(x0, pwih0, bih0, gx0, E_);

    // layer 0 recurrence (persistent)
    k_rec_persist<<<NCTA, 256, REC_SMEM>>>(whh0, gx0, bhh0, h0, y0, out, bar0);

    // layer 1 input projection: [65536,1024] x [1024->3072]
    k_gemm<<<dim3(24, 512), 256>>>(y0, pwih1, bih1, gx1, H_);

    // layer 1 recurrence (persistent)
    k_rec_persist<<<NCTA, 256, REC_SMEM>>>(whh1, gx1, bhh1, h1, nullptr, out + B_ * H_, bar1);
}